// round 1
// baseline (speedup 1.0000x reference)
#include <cuda_runtime.h>
#include <stdint.h>

// 512 x 512 voxel grid over [-51.2, 51.2)^2 at 0.2m
#define GRID_W   512
#define CELLS    (GRID_W * GRID_W)   // 262144
#define NWORDS   (CELLS / 32)        // 8192
#define MAXPTS   16384
#define EPS2     2.25f               // unused numerically: 3x3 neighborhood
#define MIN_SAMPLES   5
#define MIN_P_CLUSTER 20

// -------- device scratch (no allocations allowed) --------
__device__ unsigned char g_occ[CELLS];
__device__ unsigned char g_core[CELLS];
__device__ int           g_parent[CELLS];
__device__ int           g_raw[CELLS];     // root cell id per occupied cell, or -1
__device__ int           g_count[CELLS];   // voxel count per root cell id
__device__ unsigned int  g_mask[NWORDS];   // bitmask of root cell ids
__device__ int           g_wpref[NWORDS];  // exclusive prefix popcount of g_mask
__device__ int           g_ptcell[MAXPTS]; // cell id per point
__device__ int           g_maxDense;       // max kept dense label

// -------- kernels --------

__global__ void k_clear() {
    int i = blockIdx.x * blockDim.x + threadIdx.x;
    if (i < CELLS) {
        g_occ[i] = 0;
        g_core[i] = 0;
        g_count[i] = 0;
    }
    if (i < NWORDS) g_mask[i] = 0u;
    if (i == 0) g_maxDense = -1;
}

__global__ void k_scatter(const float* __restrict__ pts, int n) {
    int i = blockIdx.x * blockDim.x + threadIdx.x;
    if (i >= n) return;
    float x = pts[i * 5 + 1];
    float y = pts[i * 5 + 2];
    // must match jnp: floor((p - (-51.2)) / 0.2) in fp32, IEEE div
    int cx = (int)floorf((x - (-51.2f)) / 0.2f);
    int cy = (int)floorf((y - (-51.2f)) / 0.2f);
    cx = min(max(cx, 0), GRID_W - 1);
    cy = min(max(cy, 0), GRID_W - 1);
    int cell = cy * GRID_W + cx;
    g_occ[cell] = 1;
    g_ptcell[i] = cell;
}

__global__ void k_core() {
    int c = blockIdx.x * blockDim.x + threadIdx.x;
    if (c >= CELLS) return;
    g_parent[c] = c;
    if (!g_occ[c]) return;
    int cx = c & (GRID_W - 1);
    int cy = c >> 9;
    int deg = 0;
#pragma unroll
    for (int dy = -1; dy <= 1; dy++) {
#pragma unroll
        for (int dx = -1; dx <= 1; dx++) {
            int nx = cx + dx, ny = cy + dy;
            if (nx >= 0 && nx < GRID_W && ny >= 0 && ny < GRID_W)
                deg += g_occ[ny * GRID_W + nx];
        }
    }
    g_core[c] = (deg >= MIN_SAMPLES) ? 1 : 0;
}

__device__ __forceinline__ int find_root_v(int v) {
    // volatile reads so concurrent CAS updates (L2) are observed; path halving
    volatile int* p = (volatile int*)g_parent;
    int cur = v;
    int par = p[cur];
    while (par != cur) {
        int gp = p[par];
        if (gp != par) g_parent[cur] = gp;  // benign racy compression
        cur = par;
        par = p[cur];
    }
    return cur;
}

__device__ __forceinline__ void union_min(int a, int b) {
    int ra = a, rb = b;
    while (true) {
        ra = find_root_v(ra);
        rb = find_root_v(rb);
        if (ra == rb) return;
        int hi = max(ra, rb);
        int lo = min(ra, rb);
        int old = atomicCAS(&g_parent[hi], hi, lo);
        if (old == hi) return;
        ra = lo;
        rb = old;
    }
}

__global__ void k_union() {
    int c = blockIdx.x * blockDim.x + threadIdx.x;
    if (c >= CELLS) return;
    if (!g_core[c]) return;
    int cx = c & (GRID_W - 1);
    int cy = c >> 9;
    // half of the 8-neighborhood (symmetric closure via both endpoints)
    const int dxs[4] = { 1, -1, 0, 1 };
    const int dys[4] = { 0,  1, 1, 1 };
#pragma unroll
    for (int k = 0; k < 4; k++) {
        int nx = cx + dxs[k], ny = cy + dys[k];
        if (nx < 0 || nx >= GRID_W || ny < 0 || ny >= GRID_W) continue;
        int nc = ny * GRID_W + nx;
        if (g_core[nc]) union_min(c, nc);
    }
}

__device__ __forceinline__ int find_root_ro(int v) {
    int cur = v;
    while (g_parent[cur] != cur) cur = g_parent[cur];
    return cur;
}

__global__ void k_raw() {
    int c = blockIdx.x * blockDim.x + threadIdx.x;
    if (c >= CELLS) return;
    if (!g_occ[c]) return;
    int r;
    if (g_core[c]) {
        r = find_root_ro(c);
    } else {
        int cx = c & (GRID_W - 1);
        int cy = c >> 9;
        r = 0x7fffffff;
#pragma unroll
        for (int dy = -1; dy <= 1; dy++) {
#pragma unroll
            for (int dx = -1; dx <= 1; dx++) {
                if (dx == 0 && dy == 0) continue;
                int nx = cx + dx, ny = cy + dy;
                if (nx < 0 || nx >= GRID_W || ny < 0 || ny >= GRID_W) continue;
                int nc = ny * GRID_W + nx;
                if (g_core[nc]) r = min(r, find_root_ro(nc));
            }
        }
        if (r == 0x7fffffff) r = -1;
    }
    g_raw[c] = r;
    if (r >= 0) atomicAdd(&g_count[r], 1);
}

__global__ void k_mask() {
    int c = blockIdx.x * blockDim.x + threadIdx.x;
    if (c >= CELLS) return;
    if (g_count[c] > 0)
        atomicOr(&g_mask[c >> 5], 1u << (c & 31));
}

// one block, 1024 threads, 8 words/thread: exclusive prefix popcount over g_mask
__global__ void k_scan() {
    __shared__ int ssum[1024];
    int t = threadIdx.x;
    int base = t * 8;
    int pc[8];
    int s = 0;
#pragma unroll
    for (int j = 0; j < 8; j++) {
        pc[j] = __popc(g_mask[base + j]);
        s += pc[j];
    }
    ssum[t] = s;
    __syncthreads();
    // Hillis-Steele inclusive scan of thread sums
    for (int off = 1; off < 1024; off <<= 1) {
        int v = (t >= off) ? ssum[t - off] : 0;
        __syncthreads();
        ssum[t] += v;
        __syncthreads();
    }
    int run = ssum[t] - s;  // exclusive prefix for this thread's first word
#pragma unroll
    for (int j = 0; j < 8; j++) {
        g_wpref[base + j] = run;
        run += pc[j];
    }
}

__global__ void k_points_out(float* __restrict__ out, int n) {
    int i = blockIdx.x * blockDim.x + threadIdx.x;
    if (i >= n) return;
    int c = g_ptcell[i];
    int r = g_raw[c];
    int lab = -1;
    if (r >= 0 && g_count[r] >= MIN_P_CLUSTER) {
        lab = g_wpref[r >> 5] + __popc(g_mask[r >> 5] & ((1u << (r & 31)) - 1u));
        atomicMax(&g_maxDense, lab);
    }
    out[i] = (float)lab;
}

__global__ void k_tail(float* __restrict__ out, int n, int out_size) {
    int i = blockIdx.x * blockDim.x + threadIdx.x;
    int idx = n + i;
    if (idx >= out_size) return;
    out[idx] = (idx == n) ? (float)(g_maxDense + 1) : 0.0f;
}

// -------- launch --------
extern "C" void kernel_launch(void* const* d_in, const int* in_sizes, int n_in,
                              void* d_out, int out_size) {
    const float* pts = (const float*)d_in[0];
    int n = in_sizes[0] / 5;  // points are (N, 5)
    float* out = (float*)d_out;

    const int TB = 256;
    int cellBlocks = (CELLS + TB - 1) / TB;
    int ptBlocks = (n + TB - 1) / TB;

    k_clear<<<cellBlocks, TB>>>();
    k_scatter<<<ptBlocks, TB>>>(pts, n);
    k_core<<<cellBlocks, TB>>>();
    k_union<<<cellBlocks, TB>>>();
    k_raw<<<cellBlocks, TB>>>();
    k_mask<<<cellBlocks, TB>>>();
    k_scan<<<1, 1024>>>();
    k_points_out<<<ptBlocks, TB>>>(out, n);
    if (out_size > n) {
        int tail = out_size - n;
        k_tail<<<(tail + TB - 1) / TB, TB>>>(out, n, out_size);
    }
}

// round 2
// speedup vs baseline: 1.1751x; 1.1751x over previous
#include <cuda_runtime.h>
#include <stdint.h>

// 512 x 512 voxel grid over [-51.2, 51.2)^2 at 0.2m
#define GRID_W   512
#define CELLS    (GRID_W * GRID_W)   // 262144
#define NWORDS   (CELLS / 32)        // 8192
#define MAXPTS   16384
#define MIN_SAMPLES   5
#define MIN_P_CLUSTER 20

// -------- device scratch (no allocations allowed) --------
__device__ int           g_occ[CELLS];
__device__ unsigned char g_core[CELLS];
__device__ int           g_parent[CELLS];
__device__ int           g_raw[CELLS];     // root cell id per occupied cell, or -1
__device__ int           g_count[CELLS];   // voxel count per root cell id
__device__ unsigned int  g_mask[NWORDS];   // bitmask of root cell ids
__device__ int           g_wpref[NWORDS];  // exclusive prefix popcount of g_mask
__device__ int           g_list[MAXPTS];   // compacted occupied cell ids
__device__ int           g_ncells;
__device__ int           g_ptcell[MAXPTS]; // cell id per point

// -------- kernels --------

__global__ void k_clear() {
    int i = blockIdx.x * blockDim.x + threadIdx.x;
    if (i < CELLS) {
        g_occ[i] = 0;
        g_count[i] = 0;
    }
    if (i < NWORDS) g_mask[i] = 0u;
    if (i == 0) g_ncells = 0;
}

__global__ void k_scatter(const float* __restrict__ pts, int n) {
    int i = blockIdx.x * blockDim.x + threadIdx.x;
    if (i >= n) return;
    float x = pts[i * 5 + 1];
    float y = pts[i * 5 + 2];
    // match jnp: floor((p - (-51.2)) / 0.2) in fp32, IEEE div
    int cx = (int)floorf((x - (-51.2f)) / 0.2f);
    int cy = (int)floorf((y - (-51.2f)) / 0.2f);
    cx = min(max(cx, 0), GRID_W - 1);
    cy = min(max(cy, 0), GRID_W - 1);
    int cell = cy * GRID_W + cx;
    g_ptcell[i] = cell;
    if (atomicExch(&g_occ[cell], 1) == 0) {
        int p = atomicAdd(&g_ncells, 1);
        g_list[p] = cell;
        g_parent[cell] = cell;
    }
}

__device__ __forceinline__ bool is_core(int cx, int cy) {
    // g_occ[cy*GRID_W+cx] is known occupied for callers' own cell, but check
    // anyway for the neighbor case.
    if (!g_occ[cy * GRID_W + cx]) return false;
    int deg = 0;
#pragma unroll
    for (int dy = -1; dy <= 1; dy++) {
#pragma unroll
        for (int dx = -1; dx <= 1; dx++) {
            int nx = cx + dx, ny = cy + dy;
            if (nx >= 0 && nx < GRID_W && ny >= 0 && ny < GRID_W)
                deg += g_occ[ny * GRID_W + nx];
        }
    }
    return deg >= MIN_SAMPLES;
}

__device__ __forceinline__ int find_root_v(int v) {
    volatile int* p = (volatile int*)g_parent;
    int cur = v;
    int par = p[cur];
    while (par != cur) {
        int gp = p[par];
        if (gp != par) g_parent[cur] = gp;  // benign racy path-halving
        cur = par;
        par = p[cur];
    }
    return cur;
}

__device__ __forceinline__ void union_min(int a, int b) {
    int ra = a, rb = b;
    while (true) {
        ra = find_root_v(ra);
        rb = find_root_v(rb);
        if (ra == rb) return;
        int hi = max(ra, rb);
        int lo = min(ra, rb);
        int old = atomicCAS(&g_parent[hi], hi, lo);
        if (old == hi) return;
        ra = lo;
        rb = old;
    }
}

// 4 threads per occupied cell: dir 0..3 covers each 8-neighbor edge once.
// Core flags computed on the fly from g_occ; dir 0 persists g_core for k_raw.
__global__ void k_union() {
    int tid = blockIdx.x * blockDim.x + threadIdx.x;
    int idx = tid >> 2;
    int dir = tid & 3;
    if (idx >= g_ncells) return;
    int c = g_list[idx];
    int cx = c & (GRID_W - 1);
    int cy = c >> 9;
    bool cc = is_core(cx, cy);
    if (dir == 0) g_core[c] = cc ? 1 : 0;
    if (!cc) return;
    const int dxs[4] = { 1, -1, 0, 1 };
    const int dys[4] = { 0,  1, 1, 1 };
    int nx = cx + dxs[dir], ny = cy + dys[dir];
    if (nx < 0 || nx >= GRID_W || ny < 0 || ny >= GRID_W) return;
    if (!is_core(nx, ny)) return;
    union_min(c, ny * GRID_W + nx);
}

__device__ __forceinline__ int find_root_ro(int v) {
    int cur = v;
    while (g_parent[cur] != cur) cur = g_parent[cur];
    return cur;
}

// raw root per occupied cell + per-root voxel count + root bitmask
__global__ void k_raw() {
    int idx = blockIdx.x * blockDim.x + threadIdx.x;
    if (idx >= g_ncells) return;
    int c = g_list[idx];
    int cx = c & (GRID_W - 1);
    int cy = c >> 9;
    int r;
    if (g_core[c]) {
        r = find_root_ro(c);
    } else {
        r = 0x7fffffff;
#pragma unroll
        for (int dy = -1; dy <= 1; dy++) {
#pragma unroll
            for (int dx = -1; dx <= 1; dx++) {
                if (dx == 0 && dy == 0) continue;
                int nx = cx + dx, ny = cy + dy;
                if (nx < 0 || nx >= GRID_W || ny < 0 || ny >= GRID_W) continue;
                int nc = ny * GRID_W + nx;
                if (g_occ[nc] && g_core[nc]) r = min(r, find_root_ro(nc));
            }
        }
        if (r == 0x7fffffff) r = -1;
    }
    g_raw[c] = r;
    if (r >= 0) {
        if (atomicAdd(&g_count[r], 1) == 0)
            atomicOr(&g_mask[r >> 5], 1u << (r & 31));
    }
}

// single block, 1024 threads: exclusive prefix popcount over g_mask,
// plus max kept-cluster rank, plus the output tail (out[n] = max_num_inst).
__global__ void k_scan(float* __restrict__ out, int n, int out_size) {
    __shared__ int ssum[1024];
    __shared__ int smax[1024];
    int t = threadIdx.x;
    int base = t * 8;
    unsigned int w[8];
    int pc[8];
    int s = 0;
#pragma unroll
    for (int j = 0; j < 8; j++) {
        w[j] = g_mask[base + j];
        pc[j] = __popc(w[j]);
        s += pc[j];
    }
    ssum[t] = s;
    __syncthreads();
    for (int off = 1; off < 1024; off <<= 1) {
        int v = (t >= off) ? ssum[t - off] : 0;
        __syncthreads();
        ssum[t] += v;
        __syncthreads();
    }
    int run = ssum[t] - s;  // exclusive prefix of this thread's first word
    int localMax = -1;
#pragma unroll
    for (int j = 0; j < 8; j++) {
        g_wpref[base + j] = run;
        unsigned int bits = w[j];
        int rank = run;
        while (bits) {
            int b = __ffs(bits) - 1;
            bits &= bits - 1;
            int cell = (base + j) * 32 + b;
            if (g_count[cell] >= MIN_P_CLUSTER) localMax = max(localMax, rank);
            rank++;
        }
        run += pc[j];
    }
    smax[t] = localMax;
    __syncthreads();
    for (int off = 512; off > 0; off >>= 1) {
        if (t < off) smax[t] = max(smax[t], smax[t + off]);
        __syncthreads();
    }
    // tail: out[n] = max_num_inst, pad the rest with zeros
    for (int idx = n + t; idx < out_size; idx += 1024)
        out[idx] = (idx == n) ? (float)(smax[0] + 1) : 0.0f;
}

__global__ void k_points_out(float* __restrict__ out, int n) {
    int i = blockIdx.x * blockDim.x + threadIdx.x;
    if (i >= n) return;
    int c = g_ptcell[i];
    int r = g_raw[c];
    int lab = -1;
    if (r >= 0 && g_count[r] >= MIN_P_CLUSTER)
        lab = g_wpref[r >> 5] + __popc(g_mask[r >> 5] & ((1u << (r & 31)) - 1u));
    out[i] = (float)lab;
}

// -------- launch --------
extern "C" void kernel_launch(void* const* d_in, const int* in_sizes, int n_in,
                              void* d_out, int out_size) {
    const float* pts = (const float*)d_in[0];
    int n = in_sizes[0] / 5;  // points are (N, 5)
    float* out = (float*)d_out;

    const int TB = 256;
    int cellBlocks = (CELLS + TB - 1) / TB;
    int ptBlocks = (n + TB - 1) / TB;
    int unionBlocks = (4 * n + TB - 1) / TB;  // upper bound: ncells <= n

    k_clear<<<cellBlocks, TB>>>();
    k_scatter<<<ptBlocks, TB>>>(pts, n);
    k_union<<<unionBlocks, TB>>>();
    k_raw<<<ptBlocks, TB>>>();
    k_scan<<<1, 1024>>>(out, n, out_size);
    k_points_out<<<ptBlocks, TB>>>(out, n);
}